// round 9
// baseline (speedup 1.0000x reference)
#include <cuda_runtime.h>
#include <cuda_bf16.h>
#include <cstdint>
#include <cstddef>

#define H    256
#define G    4096
#define NPB  128      // nodes per scatter block
#define NMAX 500224   // capacity for per-node scratch (N = 500000)
#define BRM  64       // GEMM tile rows per CTA
#define STHB 144      // smem row stride in bytes (72 halves; conflict-free LDSM)

// SMEM layout per CTA (bytes)
#define SA        0         // A hi: + buf*9216 ; A lo: +18432 + buf*9216
#define SA_LO     18432
#define SB        36864     // B hi: + buf*18432 ; B lo: +36864 + buf*18432
#define SB_LO     36864
#define SM_SCB    110592    // float[4][64]
#define SM_TOT    111616

// -------- scratch (device globals: no allocation allowed) --------
__device__ float g_scores[NMAX];
__device__ int   g_segmax[G];
__device__ float g_sumexp[G];
__device__ float g_inv[G];
__device__ __nv_bfloat16 g_Wt_hi[H * H];   // W1^T hi: [n][k]
__device__ __nv_bfloat16 g_Wt_lo[H * H];   // W1^T lo: [n][k]

// -------- batch dtype detection (int32 vs int64) --------
__device__ __forceinline__ bool batch_is64(const void* b, int N) {
    return ((const int*)b)[N - 1] == 0;
}
__device__ __forceinline__ int get_batch(const void* b, int i, bool is64) {
    int g = is64 ? (int)((const long long*)b)[i] : ((const int*)b)[i];
    return (int)min((unsigned)g, (unsigned)(G - 1));
}

__device__ __forceinline__ uint32_t smem_u32(const void* p) {
    uint32_t a;
    asm("{ .reg .u64 t; cvta.to.shared.u64 t, %1; cvt.u32.u64 %0, t; }" : "=r"(a) : "l"(p));
    return a;
}

// -------- mma.sync m16n8k16 bf16 (baseline ISA) --------
__device__ __forceinline__ void mma16816(float* c, const uint32_t* a,
                                         uint32_t b0, uint32_t b1) {
    asm volatile(
        "mma.sync.aligned.m16n8k16.row.col.f32.bf16.bf16.f32 "
        "{%0,%1,%2,%3}, {%4,%5,%6,%7}, {%8,%9}, {%0,%1,%2,%3};"
        : "+f"(c[0]), "+f"(c[1]), "+f"(c[2]), "+f"(c[3])
        : "r"(a[0]), "r"(a[1]), "r"(a[2]), "r"(a[3]), "r"(b0), "r"(b1));
}
#define LDMX4(r, a) \
    asm volatile("ldmatrix.sync.aligned.m8n8.x4.shared.b16 {%0,%1,%2,%3}, [%4];" \
        : "=r"((r)[0]), "=r"((r)[1]), "=r"((r)[2]), "=r"((r)[3]) : "r"(a))
__device__ __forceinline__ void cp16(uint32_t dst, const void* src) {
    asm volatile("cp.async.cg.shared.global [%0], [%1], 16;" :: "r"(dst), "l"(src) : "memory");
}
#define CP_COMMIT() asm volatile("cp.async.commit_group;" ::: "memory")
#define CP_WAIT0()  asm volatile("cp.async.wait_group 0;" ::: "memory")

// pack 2 fp32 -> bf16x2 hi and lo words
__device__ __forceinline__ void split2(float v0, float v1, uint32_t& hi, uint32_t& lo) {
    __nv_bfloat16 h0 = __float2bfloat16(v0), h1 = __float2bfloat16(v1);
    float l0 = v0 - __bfloat162float(h0), l1 = v1 - __bfloat162float(h1);
    __nv_bfloat16 g0 = __float2bfloat16(l0), g1 = __float2bfloat16(l1);
    hi = ((uint32_t)__bfloat16_as_ushort(h1) << 16) | __bfloat16_as_ushort(h0);
    lo = ((uint32_t)__bfloat16_as_ushort(g1) << 16) | __bfloat16_as_ushort(g0);
}

// -------- pass 0a: zero output + score accumulator --------
__global__ void k_init_out(float* __restrict__ out, int out_size) {
    int i = blockIdx.x * blockDim.x + threadIdx.x;
    if (i < out_size) out[i] = 0.0f;
    if (i < NMAX) g_scores[i] = 0.0f;
}
__global__ void k_init_seg() {
    int i = blockIdx.x * blockDim.x + threadIdx.x;
    if (i < G) { g_segmax[i] = 0; g_sumexp[i] = 0.0f; }
}

// -------- prep: W1 [k][n] fp32 -> transposed bf16 hi/lo [n][k] --------
__global__ void k_prep_w(const float* __restrict__ W1) {
    int k = blockIdx.x, n = threadIdx.x;
    float w = W1[k * H + n];
    __nv_bfloat16 h = __float2bfloat16(w);
    float l = w - __bfloat162float(h);
    g_Wt_hi[n * H + k] = h;
    g_Wt_lo[n * H + k] = __float2bfloat16(l);
}

// -------- pass A: mma.sync GEMM, M=64 x N=128 per CTA, 2 CTAs/SM --------
__global__ __launch_bounds__(512, 2)
void k_gemm_mma(const float* __restrict__ x,
                const float* __restrict__ b1, const float* __restrict__ w2, int N)
{
    extern __shared__ __align__(16) char smem[];
    const uint32_t sbase = smem_u32(smem);
    const int t    = threadIdx.x;
    const int lane = t & 31;
    const int wid  = t >> 5;
    const int wm   = wid & 3;        // M sixteenth: rows [wm*16, wm*16+16)
    const int wn   = wid >> 2;       // N eighth: cols [wn*32, wn*32+32) within half
    const int gq   = lane >> 2;
    const int tg   = lane & 3;
    const int rowbase = (blockIdx.x >> 1) * BRM;
    const int nh      = blockIdx.x & 1;           // which N-half of W

    const uint32_t a_off = (uint32_t)((wm * 16 + (lane & 15)) * STHB + (lane >> 4) * 16);
    const uint32_t b_off = (uint32_t)((wn * 32 + ((lane >> 4) << 3) + (lane & 7)) * STHB
                                      + ((lane >> 3) & 1) * 16);

    float C[4][4];
#pragma unroll
    for (int nt = 0; nt < 4; nt++)
#pragma unroll
        for (int r = 0; r < 4; r++) C[nt][r] = 0.f;

    // ---- helpers: 512 threads; A chunk 64x64 fp32 = 1024 float4 ----
    auto loadA = [&](int k0, float4* v) {
#pragma unroll
        for (int i = 0; i < 2; i++) {
            int idx = t + i * 512;            // 0..1023
            int r = idx >> 4, q = idx & 15;
            int grow = rowbase + r;
            float4 vv = make_float4(0.f, 0.f, 0.f, 0.f);
            if (grow < N)
                vv = *reinterpret_cast<const float4*>(x + (size_t)grow * H + k0 + q * 4);
            v[i] = vv;
        }
    };
    auto storeA = [&](int buf, const float4* v) {
        char* base = smem + SA + buf * 9216;
#pragma unroll
        for (int i = 0; i < 2; i++) {
            int idx = t + i * 512;
            int r = idx >> 4, q = idx & 15;
            uint32_t h0, l0, h1, l1;
            split2(v[i].x, v[i].y, h0, l0);
            split2(v[i].z, v[i].w, h1, l1);
            *reinterpret_cast<uint2*>(base + r * STHB + q * 8)         = make_uint2(h0, h1);
            *reinterpret_cast<uint2*>(base + SA_LO + r * STHB + q * 8) = make_uint2(l0, l1);
        }
    };
    auto loadB = [&](int k0, int buf) {
        uint32_t base = sbase + SB + buf * 18432;
#pragma unroll
        for (int i = 0; i < 2; i++) {
            int idx = t + i * 512;            // 0..1023
            int n = idx >> 3, j = idx & 7;    // local row n (0..127), 16B group
            uint32_t dst = base + (uint32_t)(n * STHB + j * 16);
            int nglob = nh * 128 + n;
            cp16(dst,         g_Wt_hi + nglob * H + k0 + j * 8);
            cp16(dst + SB_LO, g_Wt_lo + nglob * H + k0 + j * 8);
        }
    };

    // ---- prologue: fill buffer 0 ----
    {
        float4 a[2];
        loadA(0, a);
        loadB(0, 0);
        CP_COMMIT();
        storeA(0, a);
    }

    for (int c = 0; c < 4; c++) {
        const int buf = c & 1;
        const uint32_t sa = sbase + SA + buf * 9216;
        const uint32_t sb = sbase + SB + buf * 18432;

        CP_WAIT0();
        __syncthreads();               // buffer c ready

        float4 a[2];
        const bool pf = (c < 3);
        if (pf) {
            loadB((c + 1) * 64, buf ^ 1);
            CP_COMMIT();
            loadA((c + 1) * 64, a);
        }

        // ---- compute chunk c: 4 k16-steps; 12 MMAs each ----
#pragma unroll
        for (int ks = 0; ks < 4; ks++) {
            uint32_t Ah[4], Al[4];
            uint32_t aaddr = sa + a_off + ks * 32;
            LDMX4(Ah, aaddr);
            LDMX4(Al, aaddr + SA_LO);
            uint32_t Bh[2][4], Bl[2][4];
#pragma unroll
            for (int q = 0; q < 2; q++) {
                uint32_t baddr = sb + b_off + q * (16 * STHB) + ks * 32;
                LDMX4(Bh[q], baddr);
                LDMX4(Bl[q], baddr + SB_LO);
            }
            // term-major: 4 independent accumulators per group
#pragma unroll
            for (int q = 0; q < 2; q++) {
                mma16816(C[2 * q],     Ah, Bh[q][0], Bh[q][1]);
                mma16816(C[2 * q + 1], Ah, Bh[q][2], Bh[q][3]);
            }
#pragma unroll
            for (int q = 0; q < 2; q++) {
                mma16816(C[2 * q],     Al, Bh[q][0], Bh[q][1]);
                mma16816(C[2 * q + 1], Al, Bh[q][2], Bh[q][3]);
            }
#pragma unroll
            for (int q = 0; q < 2; q++) {
                mma16816(C[2 * q],     Ah, Bl[q][0], Bl[q][1]);
                mma16816(C[2 * q + 1], Ah, Bl[q][2], Bl[q][3]);
            }
        }

        if (pf) storeA(buf ^ 1, a);
    }

    // ---- epilogue: tanh + w2 dot over this CTA's 128 cols (partial) ----
    float (*scb)[64] = (float(*)[64])(smem + SM_SCB);
    {
        float p0 = 0.f, p1 = 0.f;      // rows wm*16+gq, +8
#pragma unroll
        for (int nt = 0; nt < 4; nt++) {
            int col0 = nh * 128 + wn * 32 + nt * 8 + tg * 2;
            float bb0 = __ldg(b1 + col0), bb1 = __ldg(b1 + col0 + 1);
            float ww0 = __ldg(w2 + col0), ww1 = __ldg(w2 + col0 + 1);
            p0 += tanhf(C[nt][0] + bb0) * ww0 + tanhf(C[nt][1] + bb1) * ww1;
            p1 += tanhf(C[nt][2] + bb0) * ww0 + tanhf(C[nt][3] + bb1) * ww1;
        }
        p0 += __shfl_xor_sync(0xffffffffu, p0, 1);
        p0 += __shfl_xor_sync(0xffffffffu, p0, 2);
        p1 += __shfl_xor_sync(0xffffffffu, p1, 1);
        p1 += __shfl_xor_sync(0xffffffffu, p1, 2);
        __syncthreads();               // compute done; scb region safe
        if (tg == 0) {
            int row = wm * 16 + gq;
            scb[wn][row]     = p0;
            scb[wn][row + 8] = p1;
        }
    }
    __syncthreads();
    if (t < 64) {
        float sc = scb[0][t] + scb[1][t] + scb[2][t] + scb[3][t];
        int grow = rowbase + t;
        if (grow < N) atomicAdd(&g_scores[grow], sc);   // partial over N-half
    }
}

// -------- pass B2: segmented max of completed scores --------
__global__ void k_segmax(const void* __restrict__ batch, int N)
{
    int i = blockIdx.x * blockDim.x + threadIdx.x;
    int lane = threadIdx.x & 31;
    const bool is64 = batch_is64(batch, N);
    int g = -1;
    float s = -1e30f;
    if (i < N) {
        g = get_batch(batch, i, is64);
        s = g_scores[i];
    }
    float v = s;
#pragma unroll
    for (int d = 1; d < 32; d <<= 1) {
        float ov = __shfl_up_sync(0xffffffffu, v, d);
        int   og = __shfl_up_sync(0xffffffffu, g, d);
        if (lane >= d && og == g) v = fmaxf(v, ov);
    }
    int gn = __shfl_down_sync(0xffffffffu, g, 1);
    if (g >= 0 && (lane == 31 || gn != g) && v > 0.f)
        atomicMax(&g_segmax[g], __float_as_int(v));
}

// -------- pass C: exp(score - segmax), warp-segmented sum into sumexp --------
__global__ void k_exp_sum(const void* __restrict__ batch, int N)
{
    int i = blockIdx.x * blockDim.x + threadIdx.x;
    int lane = threadIdx.x & 31;
    const bool is64 = batch_is64(batch, N);
    int g = -1;
    float e = 0.f;
    if (i < N) {
        g = get_batch(batch, i, is64);
        float m = __int_as_float(g_segmax[g]);
        e = expf(g_scores[i] - m);
        g_scores[i] = e;
    }
    float v = e;
#pragma unroll
    for (int d = 1; d < 32; d <<= 1) {
        float ov = __shfl_up_sync(0xffffffffu, v, d);
        int   og = __shfl_up_sync(0xffffffffu, g, d);
        if (lane >= d && og == g) v += ov;
    }
    int gn = __shfl_down_sync(0xffffffffu, g, 1);
    if (g >= 0 && (lane == 31 || gn != g))
        atomicAdd(&g_sumexp[g], v);
}

// -------- pass D: reciprocal --------
__global__ void k_inv()
{
    int i = blockIdx.x * blockDim.x + threadIdx.x;
    if (i < G) {
        float s = g_sumexp[i];
        g_inv[i] = (s > 0.f) ? 1.0f / s : 0.f;
    }
}

// -------- pass E: out[g] += x[i] * (exp_i * inv[g]); float4, 4 row-partitions --------
__global__ void k_scatter(const float* __restrict__ x, const void* __restrict__ batch,
                          float* __restrict__ out, int N)
{
    const int tc = threadIdx.x & 63;       // column group: cols [4tc, 4tc+3]
    const int tp = threadIdx.x >> 6;       // row partition 0..3 (32 rows each)
    const int col = tc * 4;
    int i0 = blockIdx.x * NPB + tp * 32;
    if (i0 >= N) return;
    int i1 = min(i0 + 32, N);
    const bool is64 = batch_is64(batch, N);

    int gfirst = get_batch(batch, i0, is64);
    int gcur = gfirst;
    float4 acc = make_float4(0.f, 0.f, 0.f, 0.f);

    for (int i = i0; i < i1; i++) {
        int g = get_batch(batch, i, is64);
        if (g != gcur) {
            float* o = out + (size_t)gcur * H + col;
            if (gcur == gfirst) {
                atomicAdd(o + 0, acc.x); atomicAdd(o + 1, acc.y);
                atomicAdd(o + 2, acc.z); atomicAdd(o + 3, acc.w);
            } else {
                *reinterpret_cast<float4*>(o) = acc;  // exclusive interior graph
            }
            acc = make_float4(0.f, 0.f, 0.f, 0.f);
            gcur = g;
        }
        float w = g_scores[i] * g_inv[g];
        float4 v = *reinterpret_cast<const float4*>(x + (size_t)i * H + col);
        acc.x += v.x * w; acc.y += v.y * w; acc.z += v.z * w; acc.w += v.w * w;
    }
    float* o = out + (size_t)gcur * H + col;
    atomicAdd(o + 0, acc.x); atomicAdd(o + 1, acc.y);
    atomicAdd(o + 2, acc.z); atomicAdd(o + 3, acc.w);
}

// -------- launch --------
extern "C" void kernel_launch(void* const* d_in, const int* in_sizes, int n_in,
                              void* d_out, int out_size)
{
    const float* x     = (const float*)d_in[0];
    const void*  batch = (const void*)d_in[1];
    const float* W1    = (const float*)d_in[2];
    const float* b1    = (const float*)d_in[3];
    const float* w2    = (const float*)d_in[4];
    float* out = (float*)d_out;

    int N = in_sizes[1];

    cudaFuncSetAttribute(k_gemm_mma, cudaFuncAttributeMaxDynamicSharedMemorySize, SM_TOT);

    int zinit = (out_size > NMAX ? out_size : NMAX);
    k_init_out<<<(zinit + 255) / 256, 256>>>(out, out_size);  // pos 0
    k_init_seg<<<16, 256>>>();                                // pos 1
    k_prep_w<<<H, H>>>(W1);                                   // pos 2
    int mtiles = (N + BRM - 1) / BRM;
    k_gemm_mma<<<2 * mtiles, 512, SM_TOT>>>(x, b1, w2, N);    // pos 3 (ncu target)
    k_segmax<<<(N + 255) / 256, 256>>>(batch, N);
    k_exp_sum<<<(N + 255) / 256, 256>>>(batch, N);
    k_inv<<<(G + 255) / 256, 256>>>();
    k_scatter<<<(N + NPB - 1) / NPB, 256>>>(x, batch, out, N);
}

// round 10
// speedup vs baseline: 1.8160x; 1.8160x over previous
#include <cuda_runtime.h>
#include <cuda_fp16.h>
#include <cstdint>
#include <cstddef>

#define H    256
#define G    4096
#define NPB  128      // nodes per scatter block
#define NMAX 500224   // capacity for per-node scratch (N = 500000)
#define BRM  128      // GEMM tile rows per CTA
#define STHB 144      // smem row stride in bytes (72 halves; conflict-free LDSM)

// SMEM layout (bytes): A[2][128][144B], B[2][256][144B], scb
#define SA        0         // + buf*18432
#define SB        36864     // + buf*36864
#define SM_SCB    110592    // float[4][128]
#define SM_TOT    112640

// -------- scratch (device globals: no allocation allowed) --------
__device__ float g_scores[NMAX];
__device__ int   g_segmax[G];
__device__ float g_sumexp[G];
__device__ float g_inv[G];
__device__ __half g_Wt[H * H];   // W1^T fp16: [n][k]

// -------- batch dtype detection (int32 vs int64) --------
__device__ __forceinline__ bool batch_is64(const void* b, int N) {
    return ((const int*)b)[N - 1] == 0;
}
__device__ __forceinline__ int get_batch(const void* b, int i, bool is64) {
    int g = is64 ? (int)((const long long*)b)[i] : ((const int*)b)[i];
    return (int)min((unsigned)g, (unsigned)(G - 1));
}

__device__ __forceinline__ uint32_t smem_u32(const void* p) {
    uint32_t a;
    asm("{ .reg .u64 t; cvta.to.shared.u64 t, %1; cvt.u32.u64 %0, t; }" : "=r"(a) : "l"(p));
    return a;
}

// -------- mma.sync m16n8k16 fp16 inputs, fp32 accumulate --------
__device__ __forceinline__ void mma16816(float* c, const uint32_t* a,
                                         uint32_t b0, uint32_t b1) {
    asm volatile(
        "mma.sync.aligned.m16n8k16.row.col.f32.f16.f16.f32 "
        "{%0,%1,%2,%3}, {%4,%5,%6,%7}, {%8,%9}, {%0,%1,%2,%3};"
        : "+f"(c[0]), "+f"(c[1]), "+f"(c[2]), "+f"(c[3])
        : "r"(a[0]), "r"(a[1]), "r"(a[2]), "r"(a[3]), "r"(b0), "r"(b1));
}
#define LDMX4(r, a) \
    asm volatile("ldmatrix.sync.aligned.m8n8.x4.shared.b16 {%0,%1,%2,%3}, [%4];" \
        : "=r"((r)[0]), "=r"((r)[1]), "=r"((r)[2]), "=r"((r)[3]) : "r"(a))
__device__ __forceinline__ void cp16(uint32_t dst, const void* src) {
    asm volatile("cp.async.cg.shared.global [%0], [%1], 16;" :: "r"(dst), "l"(src) : "memory");
}
#define CP_COMMIT() asm volatile("cp.async.commit_group;" ::: "memory")
#define CP_WAIT0()  asm volatile("cp.async.wait_group 0;" ::: "memory")

__device__ __forceinline__ uint32_t pack_h2(float v0, float v1) {
    __half2 h = __float22half2_rn(make_float2(v0, v1));
    return *reinterpret_cast<uint32_t*>(&h);
}

// -------- pass 0: zero output + segment buffers --------
__global__ void k_init_out(float* __restrict__ out, int out_size) {
    int i = blockIdx.x * blockDim.x + threadIdx.x;
    if (i < out_size) out[i] = 0.0f;
}
__global__ void k_init_seg() {
    int i = blockIdx.x * blockDim.x + threadIdx.x;
    if (i < G) { g_segmax[i] = 0; g_sumexp[i] = 0.0f; }
}

// -------- prep: W1 [k][n] fp32 -> transposed fp16 [n][k] --------
__global__ void k_prep_w(const float* __restrict__ W1) {
    int k = blockIdx.x, n = threadIdx.x;
    g_Wt[n * H + k] = __float2half(W1[k * H + n]);
}

// -------- pass A: pipelined fp16 mma.sync GEMM, M=128 x N=256 per CTA --------
__global__ __launch_bounds__(512, 1)
void k_gemm_mma(const float* __restrict__ x, const void* __restrict__ batch,
                const float* __restrict__ b1, const float* __restrict__ w2, int N)
{
    extern __shared__ __align__(16) char smem[];
    const uint32_t sbase = smem_u32(smem);
    const int t    = threadIdx.x;
    const int lane = t & 31;
    const int wid  = t >> 5;
    const int wm   = wid & 3;        // M quarter (32 rows)
    const int wn   = wid >> 2;       // N quarter (64 cols)
    const int gq   = lane >> 2;
    const int tg   = lane & 3;
    const int rowbase = blockIdx.x * BRM;

    const uint32_t a_off = (uint32_t)((wm * 32 + (lane & 15)) * STHB + (lane >> 4) * 16);
    const uint32_t b_off = (uint32_t)((wn * 64 + ((lane >> 4) << 3) + (lane & 7)) * STHB
                                      + ((lane >> 3) & 1) * 16);

    float C[2][8][4];
#pragma unroll
    for (int mt = 0; mt < 2; mt++)
#pragma unroll
        for (int nt = 0; nt < 8; nt++)
#pragma unroll
            for (int r = 0; r < 4; r++) C[mt][nt][r] = 0.f;

    // ---- A: 512 threads, 4 float4 each = 128x64 fp32 ----
    auto loadA = [&](int k0, float4* v) {
#pragma unroll
        for (int i = 0; i < 4; i++) {
            int idx = t + i * 512;            // 0..2047
            int r = idx >> 4, q = idx & 15;
            int grow = rowbase + r;
            float4 vv = make_float4(0.f, 0.f, 0.f, 0.f);
            if (grow < N)
                vv = *reinterpret_cast<const float4*>(x + (size_t)grow * H + k0 + q * 4);
            v[i] = vv;
        }
    };
    auto storeA = [&](int buf, const float4* v) {
        char* base = smem + SA + buf * 18432;
#pragma unroll
        for (int i = 0; i < 4; i++) {
            int idx = t + i * 512;
            int r = idx >> 4, q = idx & 15;
            uint32_t h0 = pack_h2(v[i].x, v[i].y);
            uint32_t h1 = pack_h2(v[i].z, v[i].w);
            *reinterpret_cast<uint2*>(base + r * STHB + q * 8) = make_uint2(h0, h1);
        }
    };
    auto loadB = [&](int k0, int buf) {
        uint32_t base = sbase + SB + buf * 36864;
#pragma unroll
        for (int i = 0; i < 4; i++) {
            int idx = t + i * 512;            // 0..2047
            int n = idx >> 3, j = idx & 7;
            cp16(base + (uint32_t)(n * STHB + j * 16), g_Wt + n * H + k0 + j * 8);
        }
    };

    // ---- prologue: fill buffer 0 ----
    {
        float4 a[4];
        loadA(0, a);
        loadB(0, 0);
        CP_COMMIT();
        storeA(0, a);
    }

    for (int c = 0; c < 4; c++) {
        const int buf = c & 1;
        const uint32_t sa = sbase + SA + buf * 18432;
        const uint32_t sb = sbase + SB + buf * 36864;

        CP_WAIT0();
        __syncthreads();           // buffer c ready (cp.async B + STS A)

        float4 a[4];
        const bool pf = (c < 3);
        if (pf) {
            loadB((c + 1) * 64, buf ^ 1);   // overlaps compute below
            CP_COMMIT();
            loadA((c + 1) * 64, a);         // LDG latency hidden by compute
        }

        // ---- compute chunk c: 4 k16-steps, 16 MMAs each ----
#pragma unroll
        for (int ks = 0; ks < 4; ks++) {
            uint32_t Ah[2][4];
#pragma unroll
            for (int mt = 0; mt < 2; mt++)
                LDMX4(Ah[mt], sa + a_off + mt * (16 * STHB) + ks * 32);
#pragma unroll
            for (int p = 0; p < 4; p++) {
                uint32_t Bh[4];
                LDMX4(Bh, sb + b_off + p * (16 * STHB) + ks * 32);
#pragma unroll
                for (int mt = 0; mt < 2; mt++) {
                    mma16816(C[mt][2 * p],     Ah[mt], Bh[0], Bh[1]);
                    mma16816(C[mt][2 * p + 1], Ah[mt], Bh[2], Bh[3]);
                }
            }
        }

        if (pf) storeA(buf ^ 1, a);    // next-iter sync publishes it
    }

    // ---- epilogue: tanh + w2 dot, reduce over frag lanes + N-warps ----
    float (*scb)[128] = (float(*)[128])(smem + SM_SCB);
#pragma unroll
    for (int mt = 0; mt < 2; mt++) {
        float p0 = 0.f, p1 = 0.f;           // rows wm*32+mt*16+gq, +8
#pragma unroll
        for (int nt = 0; nt < 8; nt++) {
            int col0 = wn * 64 + nt * 8 + tg * 2;
            float bb0 = __ldg(b1 + col0), bb1 = __ldg(b1 + col0 + 1);
            float ww0 = __ldg(w2 + col0), ww1 = __ldg(w2 + col0 + 1);
            p0 += tanhf(C[mt][nt][0] + bb0) * ww0 + tanhf(C[mt][nt][1] + bb1) * ww1;
            p1 += tanhf(C[mt][nt][2] + bb0) * ww0 + tanhf(C[mt][nt][3] + bb1) * ww1;
        }
        p0 += __shfl_xor_sync(0xffffffffu, p0, 1);
        p0 += __shfl_xor_sync(0xffffffffu, p0, 2);
        p1 += __shfl_xor_sync(0xffffffffu, p1, 1);
        p1 += __shfl_xor_sync(0xffffffffu, p1, 2);
        if (mt == 0) __syncthreads();       // compute done; scb aliasing safe
        if (tg == 0) {
            int row = wm * 32 + mt * 16 + gq;
            scb[wn][row]     = p0;
            scb[wn][row + 8] = p1;
        }
    }
    __syncthreads();
    if (t < 128) {
        float sc = scb[0][t] + scb[1][t] + scb[2][t] + scb[3][t];
        int grow = rowbase + t;
        if (grow < N) {
            g_scores[grow] = sc;
            if (sc > 0.f) {
                const bool is64 = batch_is64(batch, N);
                atomicMax(&g_segmax[get_batch(batch, grow, is64)], __float_as_int(sc));
            }
        }
    }
}

// -------- pass C: exp(score - segmax), warp-segmented sum into sumexp --------
__global__ void k_exp_sum(const void* __restrict__ batch, int N)
{
    int i = blockIdx.x * blockDim.x + threadIdx.x;
    int lane = threadIdx.x & 31;
    const bool is64 = batch_is64(batch, N);
    int g = -1;
    float e = 0.f;
    if (i < N) {
        g = get_batch(batch, i, is64);
        float m = __int_as_float(g_segmax[g]);
        e = expf(g_scores[i] - m);
        g_scores[i] = e;
    }
    float v = e;
#pragma unroll
    for (int d = 1; d < 32; d <<= 1) {
        float ov = __shfl_up_sync(0xffffffffu, v, d);
        int   og = __shfl_up_sync(0xffffffffu, g, d);
        if (lane >= d && og == g) v += ov;
    }
    int gn = __shfl_down_sync(0xffffffffu, g, 1);
    if (g >= 0 && (lane == 31 || gn != g))
        atomicAdd(&g_sumexp[g], v);
}

// -------- pass D: reciprocal --------
__global__ void k_inv()
{
    int i = blockIdx.x * blockDim.x + threadIdx.x;
    if (i < G) {
        float s = g_sumexp[i];
        g_inv[i] = (s > 0.f) ? 1.0f / s : 0.f;
    }
}

// -------- pass E: out[g] += x[i] * (exp_i * inv[g]); float4, 4 row-partitions --------
__global__ void k_scatter(const float* __restrict__ x, const void* __restrict__ batch,
                          float* __restrict__ out, int N)
{
    const int tc = threadIdx.x & 63;       // column group: cols [4tc, 4tc+3]
    const int tp = threadIdx.x >> 6;       // row partition 0..3 (32 rows each)
    const int col = tc * 4;
    int i0 = blockIdx.x * NPB + tp * 32;
    if (i0 >= N) return;
    int i1 = min(i0 + 32, N);
    const bool is64 = batch_is64(batch, N);

    int gfirst = get_batch(batch, i0, is64);
    int gcur = gfirst;
    float4 acc = make_float4(0.f, 0.f, 0.f, 0.f);

    for (int i = i0; i < i1; i++) {
        int g = get_batch(batch, i, is64);
        if (g != gcur) {
            float* o = out + (size_t)gcur * H + col;
            if (gcur == gfirst) {
                atomicAdd(o + 0, acc.x); atomicAdd(o + 1, acc.y);
                atomicAdd(o + 2, acc.z); atomicAdd(o + 3, acc.w);
            } else {
                *reinterpret_cast<float4*>(o) = acc;  // exclusive interior graph
            }
            acc = make_float4(0.f, 0.f, 0.f, 0.f);
            gcur = g;
        }
        float w = g_scores[i] * g_inv[g];
        float4 v = *reinterpret_cast<const float4*>(x + (size_t)i * H + col);
        acc.x += v.x * w; acc.y += v.y * w; acc.z += v.z * w; acc.w += v.w * w;
    }
    float* o = out + (size_t)gcur * H + col;
    atomicAdd(o + 0, acc.x); atomicAdd(o + 1, acc.y);
    atomicAdd(o + 2, acc.z); atomicAdd(o + 3, acc.w);
}

// -------- launch --------
extern "C" void kernel_launch(void* const* d_in, const int* in_sizes, int n_in,
                              void* d_out, int out_size)
{
    const float* x     = (const float*)d_in[0];
    const void*  batch = (const void*)d_in[1];
    const float* W1    = (const float*)d_in[2];
    const float* b1    = (const float*)d_in[3];
    const float* w2    = (const float*)d_in[4];
    float* out = (float*)d_out;

    int N = in_sizes[1];

    cudaFuncSetAttribute(k_gemm_mma, cudaFuncAttributeMaxDynamicSharedMemorySize, SM_TOT);

    int initBlocks = (out_size + 255) / 256;
    k_init_out<<<initBlocks, 256>>>(out, out_size);   // pos 0
    k_init_seg<<<16, 256>>>();                        // pos 1
    k_prep_w<<<H, H>>>(W1);                           // pos 2
    k_gemm_mma<<<(N + BRM - 1) / BRM, 512, SM_TOT>>>(x, batch, b1, w2, N);  // pos 3 (ncu target)
    k_exp_sum<<<(N + 255) / 256, 256>>>(batch, N);
    k_inv<<<(G + 255) / 256, 256>>>();
    k_scatter<<<(N + NPB - 1) / NPB, 256>>>(x, batch, out, N);
}

// round 11
// speedup vs baseline: 2.1338x; 1.1750x over previous
#include <cuda_runtime.h>
#include <cuda_fp16.h>
#include <cstdint>
#include <cstddef>

#define H    256
#define G    4096
#define NPB  128      // nodes per scatter block
#define NMAX 500224   // capacity for per-node scratch (N = 500000)
#define BRM  128      // GEMM tile rows per CTA
#define STHB 144      // A smem row stride bytes (72 halves; conflict-free LDSM)
#define SBSTR 528     // B smem row stride bytes (264 halves; 132 words mod 32 = 4 -> conflict-free)

// SMEM layout (bytes)
#define SB0    0                      // B resident: 256 x 528 = 135168
#define SA0    135168                 // A: + buf*18432 (128 x 144)
#define SM_SCB 171008                 // float[4][128] = 2048  (135168+36864+1024 pad)
#define SM_TOT 173056

// -------- scratch (device globals: no allocation allowed) --------
__device__ float g_scores[NMAX];
__device__ int   g_segmax[G];
__device__ float g_sumexp[G];
__device__ float g_inv[G];
__device__ __half g_Wt[H * H];   // W1^T fp16: [n][k]

// -------- batch dtype detection (int32 vs int64) --------
__device__ __forceinline__ bool batch_is64(const void* b, int N) {
    return ((const int*)b)[N - 1] == 0;
}
__device__ __forceinline__ int get_batch(const void* b, int i, bool is64) {
    int g = is64 ? (int)((const long long*)b)[i] : ((const int*)b)[i];
    return (int)min((unsigned)g, (unsigned)(G - 1));
}

__device__ __forceinline__ uint32_t smem_u32(const void* p) {
    uint32_t a;
    asm("{ .reg .u64 t; cvta.to.shared.u64 t, %1; cvt.u32.u64 %0, t; }" : "=r"(a) : "l"(p));
    return a;
}

// -------- mma.sync m16n8k16 fp16 inputs, fp32 accumulate --------
__device__ __forceinline__ void mma16816(float* c, const uint32_t* a,
                                         uint32_t b0, uint32_t b1) {
    asm volatile(
        "mma.sync.aligned.m16n8k16.row.col.f32.f16.f16.f32 "
        "{%0,%1,%2,%3}, {%4,%5,%6,%7}, {%8,%9}, {%0,%1,%2,%3};"
        : "+f"(c[0]), "+f"(c[1]), "+f"(c[2]), "+f"(c[3])
        : "r"(a[0]), "r"(a[1]), "r"(a[2]), "r"(a[3]), "r"(b0), "r"(b1));
}
#define LDMX4(r, a) \
    asm volatile("ldmatrix.sync.aligned.m8n8.x4.shared.b16 {%0,%1,%2,%3}, [%4];" \
        : "=r"((r)[0]), "=r"((r)[1]), "=r"((r)[2]), "=r"((r)[3]) : "r"(a))
__device__ __forceinline__ void cp16(uint32_t dst, const void* src) {
    asm volatile("cp.async.cg.shared.global [%0], [%1], 16;" :: "r"(dst), "l"(src) : "memory");
}
#define CP_COMMIT() asm volatile("cp.async.commit_group;" ::: "memory")
#define CP_WAIT0()  asm volatile("cp.async.wait_group 0;" ::: "memory")

__device__ __forceinline__ uint32_t pack_h2(float v0, float v1) {
    __half2 h = __float22half2_rn(make_float2(v0, v1));
    return *reinterpret_cast<uint32_t*>(&h);
}

// -------- pass 0: zero output + segment buffers --------
__global__ void k_init_out(float* __restrict__ out, int out_size) {
    int i = blockIdx.x * blockDim.x + threadIdx.x;
    if (i < out_size) out[i] = 0.0f;
}
__global__ void k_init_seg() {
    int i = blockIdx.x * blockDim.x + threadIdx.x;
    if (i < G) { g_segmax[i] = 0; g_sumexp[i] = 0.0f; }
}

// -------- prep: W1 [k][n] fp32 -> transposed fp16 [n][k] --------
__global__ void k_prep_w(const float* __restrict__ W1) {
    int k = blockIdx.x, n = threadIdx.x;
    g_Wt[n * H + k] = __float2half(W1[k * H + n]);
}

// -------- pass A: PERSISTENT fp16 mma.sync GEMM; W resident in SMEM --------
__global__ __launch_bounds__(512, 1)
void k_gemm_mma(const float* __restrict__ x, const void* __restrict__ batch,
                const float* __restrict__ b1, const float* __restrict__ w2,
                int N, int T, int nctas)
{
    extern __shared__ __align__(16) char smem[];
    const uint32_t sbase = smem_u32(smem);
    const int t    = threadIdx.x;
    const int lane = t & 31;
    const int wid  = t >> 5;
    const int wm   = wid & 3;        // M quarter (32 rows)
    const int wn   = wid >> 2;       // N quarter (64 cols)
    const int gq   = lane >> 2;
    const int tg   = lane & 3;
    const int bid  = blockIdx.x;
    const bool is64 = batch_is64(batch, N);

    const uint32_t a_off = (uint32_t)((wm * 32 + (lane & 15)) * STHB + (lane >> 4) * 16);
    const uint32_t b_off = (uint32_t)((wn * 64 + ((lane >> 4) << 3) + (lane & 7)) * SBSTR
                                      + ((lane >> 3) & 1) * 16);

    float C[2][8][4];
#pragma unroll
    for (int mt = 0; mt < 2; mt++)
#pragma unroll
        for (int nt = 0; nt < 8; nt++)
#pragma unroll
            for (int r = 0; r < 4; r++) C[mt][nt][r] = 0.f;

    // ---- resident B: all of Wt (256 x 256 fp16), 8192 cp16 / 512 thr ----
    {
#pragma unroll
        for (int i = 0; i < 16; i++) {
            int idx = t + i * 512;            // 0..8191
            int n = idx >> 5, j = idx & 31;   // row n, 16B group
            cp16(sbase + SB0 + (uint32_t)(n * SBSTR + j * 16), g_Wt + n * H + j * 8);
        }
        CP_COMMIT();
    }

    // number of tiles this CTA owns: tiles bid, bid+nctas, ...
    const int myT = (T - bid + nctas - 1) / nctas;
    if (myT <= 0) { CP_WAIT0(); return; }
    const int nchunks = 4 * myT;

    auto tile_rowbase = [&](int ti) { return (bid + ti * nctas) * BRM; };

    auto loadA = [&](int rowbase, int k0, float4* v) {
#pragma unroll
        for (int i = 0; i < 4; i++) {
            int idx = t + i * 512;            // 0..2047
            int r = idx >> 4, q = idx & 15;
            int grow = rowbase + r;
            float4 vv = make_float4(0.f, 0.f, 0.f, 0.f);
            if (grow < N)
                vv = *reinterpret_cast<const float4*>(x + (size_t)grow * H + k0 + q * 4);
            v[i] = vv;
        }
    };
    auto storeA = [&](int buf, const float4* v) {
        char* base = smem + SA0 + buf * 18432;
#pragma unroll
        for (int i = 0; i < 4; i++) {
            int idx = t + i * 512;
            int r = idx >> 4, q = idx & 15;
            uint32_t h0 = pack_h2(v[i].x, v[i].y);
            uint32_t h1 = pack_h2(v[i].z, v[i].w);
            *reinterpret_cast<uint2*>(base + r * STHB + q * 8) = make_uint2(h0, h1);
        }
    };

    // ---- prologue: A chunk 0 ----
    {
        float4 a[4];
        loadA(tile_rowbase(0), 0, a);
        storeA(0, a);
    }
    CP_WAIT0();      // B resident ready

    float (*scb)[128] = (float(*)[128])(smem + SM_SCB);

    for (int cc = 0; cc < nchunks; cc++) {
        const int buf = cc & 1;
        const uint32_t sa = sbase + SA0 + buf * 18432;
        const int kc = cc & 3;               // K chunk within tile

        __syncthreads();                     // buffer cc ready; prev compute done

        float4 a[4];
        const bool pf = (cc + 1 < nchunks);
        if (pf) {
            int cc2 = cc + 1;
            loadA(tile_rowbase(cc2 >> 2), (cc2 & 3) * 64, a);   // LDG overlaps compute
        }

        // ---- compute chunk: 4 k16-steps, 16 MMAs each; B from resident SMEM ----
#pragma unroll
        for (int ks = 0; ks < 4; ks++) {
            uint32_t Ah[2][4];
#pragma unroll
            for (int mt = 0; mt < 2; mt++)
                LDMX4(Ah[mt], sa + a_off + mt * (16 * STHB) + ks * 32);
            const uint32_t kbyte = (uint32_t)(kc * 128 + ks * 32);
#pragma unroll
            for (int p = 0; p < 4; p++) {
                uint32_t Bh[4];
                LDMX4(Bh, sbase + SB0 + b_off + p * (16 * SBSTR) + kbyte);
#pragma unroll
                for (int mt = 0; mt < 2; mt++) {
                    mma16816(C[mt][2 * p],     Ah[mt], Bh[0], Bh[1]);
                    mma16816(C[mt][2 * p + 1], Ah[mt], Bh[2], Bh[3]);
                }
            }
        }

        // ---- tile boundary: epilogue ----
        if (kc == 3) {
            const int rowbase = tile_rowbase(cc >> 2);
            float pr[2][2];
#pragma unroll
            for (int mt = 0; mt < 2; mt++) {
                float p0 = 0.f, p1 = 0.f;
#pragma unroll
                for (int nt = 0; nt < 8; nt++) {
                    int col0 = wn * 64 + nt * 8 + tg * 2;
                    float bb0 = __ldg(b1 + col0), bb1 = __ldg(b1 + col0 + 1);
                    float ww0 = __ldg(w2 + col0), ww1 = __ldg(w2 + col0 + 1);
                    p0 += tanhf(C[mt][nt][0] + bb0) * ww0 + tanhf(C[mt][nt][1] + bb1) * ww1;
                    p1 += tanhf(C[mt][nt][2] + bb0) * ww0 + tanhf(C[mt][nt][3] + bb1) * ww1;
                    C[mt][nt][0] = C[mt][nt][1] = C[mt][nt][2] = C[mt][nt][3] = 0.f;
                }
                p0 += __shfl_xor_sync(0xffffffffu, p0, 1);
                p0 += __shfl_xor_sync(0xffffffffu, p0, 2);
                p1 += __shfl_xor_sync(0xffffffffu, p1, 1);
                p1 += __shfl_xor_sync(0xffffffffu, p1, 2);
                pr[mt][0] = p0; pr[mt][1] = p1;
            }
            __syncthreads();                 // prior-tile scb reads done
            if (tg == 0) {
#pragma unroll
                for (int mt = 0; mt < 2; mt++) {
                    int row = wm * 32 + mt * 16 + gq;
                    scb[wn][row]     = pr[mt][0];
                    scb[wn][row + 8] = pr[mt][1];
                }
            }
            __syncthreads();
            if (t < 128) {
                float sc = scb[0][t] + scb[1][t] + scb[2][t] + scb[3][t];
                int grow = rowbase + t;
                if (grow < N) {
                    g_scores[grow] = sc;
                    if (sc > 0.f)
                        atomicMax(&g_segmax[get_batch(batch, grow, is64)], __float_as_int(sc));
                }
            }
        }

        if (pf) storeA(buf ^ 1, a);          // next-iter sync publishes it
    }
}

// -------- pass C: exp(score - segmax), warp-segmented sum into sumexp --------
__global__ void k_exp_sum(const void* __restrict__ batch, int N)
{
    int i = blockIdx.x * blockDim.x + threadIdx.x;
    int lane = threadIdx.x & 31;
    const bool is64 = batch_is64(batch, N);
    int g = -1;
    float e = 0.f;
    if (i < N) {
        g = get_batch(batch, i, is64);
        float m = __int_as_float(g_segmax[g]);
        e = expf(g_scores[i] - m);
        g_scores[i] = e;
    }
    float v = e;
#pragma unroll
    for (int d = 1; d < 32; d <<= 1) {
        float ov = __shfl_up_sync(0xffffffffu, v, d);
        int   og = __shfl_up_sync(0xffffffffu, g, d);
        if (lane >= d && og == g) v += ov;
    }
    int gn = __shfl_down_sync(0xffffffffu, g, 1);
    if (g >= 0 && (lane == 31 || gn != g))
        atomicAdd(&g_sumexp[g], v);
}

// -------- pass D: reciprocal --------
__global__ void k_inv()
{
    int i = blockIdx.x * blockDim.x + threadIdx.x;
    if (i < G) {
        float s = g_sumexp[i];
        g_inv[i] = (s > 0.f) ? 1.0f / s : 0.f;
    }
}

// -------- pass E: out[g] += x[i] * (exp_i * inv[g]); float4, 4 row-partitions --------
__global__ void k_scatter(const float* __restrict__ x, const void* __restrict__ batch,
                          float* __restrict__ out, int N)
{
    const int tc = threadIdx.x & 63;       // column group: cols [4tc, 4tc+3]
    const int tp = threadIdx.x >> 6;       // row partition 0..3 (32 rows each)
    const int col = tc * 4;
    int i0 = blockIdx.x * NPB + tp * 32;
    if (i0 >= N) return;
    int i1 = min(i0 + 32, N);
    const bool is64 = batch_is64(batch, N);

    int gfirst = get_batch(batch, i0, is64);
    int gcur = gfirst;
    float4 acc = make_float4(0.f, 0.f, 0.f, 0.f);

    for (int i = i0; i < i1; i++) {
        int g = get_batch(batch, i, is64);
        if (g != gcur) {
            float* o = out + (size_t)gcur * H + col;
            if (gcur == gfirst) {
                atomicAdd(o + 0, acc.x); atomicAdd(o + 1, acc.y);
                atomicAdd(o + 2, acc.z); atomicAdd(o + 3, acc.w);
            } else {
                *reinterpret_cast<float4*>(o) = acc;  // exclusive interior graph
            }
            acc = make_float4(0.f, 0.f, 0.f, 0.f);
            gcur = g;
        }
        float w = g_scores[i] * g_inv[g];
        float4 v = *reinterpret_cast<const float4*>(x + (size_t)i * H + col);
        acc.x += v.x * w; acc.y += v.y * w; acc.z += v.z * w; acc.w += v.w * w;
    }
    float* o = out + (size_t)gcur * H + col;
    atomicAdd(o + 0, acc.x); atomicAdd(o + 1, acc.y);
    atomicAdd(o + 2, acc.z); atomicAdd(o + 3, acc.w);
}

// -------- launch --------
extern "C" void kernel_launch(void* const* d_in, const int* in_sizes, int n_in,
                              void* d_out, int out_size)
{
    const float* x     = (const float*)d_in[0];
    const void*  batch = (const void*)d_in[1];
    const float* W1    = (const float*)d_in[2];
    const float* b1    = (const float*)d_in[3];
    const float* w2    = (const float*)d_in[4];
    float* out = (float*)d_out;

    int N = in_sizes[1];

    int nsm = 148;
    cudaDeviceGetAttribute(&nsm, cudaDevAttrMultiProcessorCount, 0);

    cudaFuncSetAttribute(k_gemm_mma, cudaFuncAttributeMaxDynamicSharedMemorySize, SM_TOT);

    int initBlocks = (out_size + 255) / 256;
    k_init_out<<<initBlocks, 256>>>(out, out_size);   // pos 0
    k_init_seg<<<16, 256>>>();                        // pos 1
    k_prep_w<<<H, H>>>(W1);                           // pos 2
    int T = (N + BRM - 1) / BRM;
    k_gemm_mma<<<nsm, 512, SM_TOT>>>(x, batch, b1, w2, N, T, nsm);  // pos 3 (ncu target)
    k_exp_sum<<<(N + 255) / 256, 256>>>(batch, N);
    k_inv<<<(G + 255) / 256, 256>>>();
    k_scatter<<<(N + NPB - 1) / NPB, 256>>>(x, batch, out, N);
}

// round 12
// speedup vs baseline: 2.1735x; 1.0186x over previous
#include <cuda_runtime.h>
#include <cuda_fp16.h>
#include <cstdint>
#include <cstddef>

#define H    256
#define G    4096
#define NPB  256      // nodes per scatter block (4 partitions x 64 rows)
#define NMAX 500224   // capacity for per-node scratch (N = 500000)
#define BRM  128      // GEMM tile rows per CTA
#define STHB 144      // A smem row stride bytes (72 halves; conflict-free LDSM)
#define SBSTR 528     // B smem row stride bytes (264 halves; conflict-free LDSM)

// SMEM layout (bytes)
#define SB0    0                      // B resident: 256 x 528 = 135168
#define SA0    135168                 // A: + buf*18432 (128 x 144)
#define SM_SCB 171008                 // float[4][128] = 2048
#define SM_TOT 173056

// -------- scratch (device globals: no allocation allowed) --------
__device__ float g_scores[NMAX];
__device__ int   g_segmax[G];
__device__ float g_sumexp[G];
__device__ float g_inv[G];
__device__ __half g_Wt[H * H];   // W1^T fp16: [n][k]

// -------- batch dtype detection (int32 vs int64) --------
__device__ __forceinline__ bool batch_is64(const void* b, int N) {
    return ((const int*)b)[N - 1] == 0;
}
__device__ __forceinline__ int get_batch(const void* b, int i, bool is64) {
    int g = is64 ? (int)((const long long*)b)[i] : ((const int*)b)[i];
    return (int)min((unsigned)g, (unsigned)(G - 1));
}

__device__ __forceinline__ uint32_t smem_u32(const void* p) {
    uint32_t a;
    asm("{ .reg .u64 t; cvta.to.shared.u64 t, %1; cvt.u32.u64 %0, t; }" : "=r"(a) : "l"(p));
    return a;
}

// fast tanh: (e^2x - 1) / (e^2x + 1), MUFU-based; |err| ~1e-6
__device__ __forceinline__ float fast_tanh(float x) {
    float xc = fminf(fmaxf(x, -15.f), 15.f);
    float e  = __expf(2.f * xc);
    return __fdividef(e - 1.f, e + 1.f);
}

// -------- mma.sync m16n8k16 fp16 inputs, fp32 accumulate --------
__device__ __forceinline__ void mma16816(float* c, const uint32_t* a,
                                         uint32_t b0, uint32_t b1) {
    asm volatile(
        "mma.sync.aligned.m16n8k16.row.col.f32.f16.f16.f32 "
        "{%0,%1,%2,%3}, {%4,%5,%6,%7}, {%8,%9}, {%0,%1,%2,%3};"
        : "+f"(c[0]), "+f"(c[1]), "+f"(c[2]), "+f"(c[3])
        : "r"(a[0]), "r"(a[1]), "r"(a[2]), "r"(a[3]), "r"(b0), "r"(b1));
}
#define LDMX4(r, a) \
    asm volatile("ldmatrix.sync.aligned.m8n8.x4.shared.b16 {%0,%1,%2,%3}, [%4];" \
        : "=r"((r)[0]), "=r"((r)[1]), "=r"((r)[2]), "=r"((r)[3]) : "r"(a))
__device__ __forceinline__ void cp16(uint32_t dst, const void* src) {
    asm volatile("cp.async.cg.shared.global [%0], [%1], 16;" :: "r"(dst), "l"(src) : "memory");
}
#define CP_COMMIT() asm volatile("cp.async.commit_group;" ::: "memory")
#define CP_WAIT0()  asm volatile("cp.async.wait_group 0;" ::: "memory")

__device__ __forceinline__ uint32_t pack_h2(float v0, float v1) {
    __half2 h = __float22half2_rn(make_float2(v0, v1));
    return *reinterpret_cast<uint32_t*>(&h);
}

// -------- pass 0: zero output + segment buffers --------
__global__ void k_init_out(float* __restrict__ out, int out_size) {
    int i = blockIdx.x * blockDim.x + threadIdx.x;
    if (i < out_size) out[i] = 0.0f;
}
__global__ void k_init_seg() {
    int i = blockIdx.x * blockDim.x + threadIdx.x;
    if (i < G) { g_segmax[i] = 0; g_sumexp[i] = 0.0f; }
}

// -------- prep: W1 [k][n] fp32 -> transposed fp16 [n][k] --------
__global__ void k_prep_w(const float* __restrict__ W1) {
    int k = blockIdx.x, n = threadIdx.x;
    g_Wt[n * H + k] = __float2half(W1[k * H + n]);
}

// -------- pass A: PERSISTENT fp16 mma.sync GEMM; W resident in SMEM --------
__global__ __launch_bounds__(512, 1)
void k_gemm_mma(const float* __restrict__ x, const void* __restrict__ batch,
                const float* __restrict__ b1, const float* __restrict__ w2,
                int N, int T, int nctas)
{
    extern __shared__ __align__(16) char smem[];
    const uint32_t sbase = smem_u32(smem);
    const int t    = threadIdx.x;
    const int lane = t & 31;
    const int wid  = t >> 5;
    const int wm   = wid & 3;        // M quarter (32 rows)
    const int wn   = wid >> 2;       // N quarter (64 cols)
    const int gq   = lane >> 2;
    const int tg   = lane & 3;
    const int bid  = blockIdx.x;
    const bool is64 = batch_is64(batch, N);

    const uint32_t a_off = (uint32_t)((wm * 32 + (lane & 15)) * STHB + (lane >> 4) * 16);
    const uint32_t b_off = (uint32_t)((wn * 64 + ((lane >> 4) << 3) + (lane & 7)) * SBSTR
                                      + ((lane >> 3) & 1) * 16);

    float C[2][8][4];
#pragma unroll
    for (int mt = 0; mt < 2; mt++)
#pragma unroll
        for (int nt = 0; nt < 8; nt++)
#pragma unroll
            for (int r = 0; r < 4; r++) C[mt][nt][r] = 0.f;

    // ---- resident B: all of Wt (256 x 256 fp16), 8192 cp16 / 512 thr ----
    {
#pragma unroll
        for (int i = 0; i < 16; i++) {
            int idx = t + i * 512;            // 0..8191
            int n = idx >> 5, j = idx & 31;   // row n, 16B group
            cp16(sbase + SB0 + (uint32_t)(n * SBSTR + j * 16), g_Wt + n * H + j * 8);
        }
        CP_COMMIT();
    }

    const int myT = (T - bid + nctas - 1) / nctas;
    if (myT <= 0) { CP_WAIT0(); return; }
    const int nchunks = 4 * myT;

    auto tile_rowbase = [&](int ti) { return (bid + ti * nctas) * BRM; };

    auto loadA = [&](int rowbase, int k0, float4* v) {
#pragma unroll
        for (int i = 0; i < 4; i++) {
            int idx = t + i * 512;            // 0..2047
            int r = idx >> 4, q = idx & 15;
            int grow = rowbase + r;
            float4 vv = make_float4(0.f, 0.f, 0.f, 0.f);
            if (grow < N)
                vv = *reinterpret_cast<const float4*>(x + (size_t)grow * H + k0 + q * 4);
            v[i] = vv;
        }
    };
    auto storeA = [&](int buf, const float4* v) {
        char* base = smem + SA0 + buf * 18432;
#pragma unroll
        for (int i = 0; i < 4; i++) {
            int idx = t + i * 512;
            int r = idx >> 4, q = idx & 15;
            uint32_t h0 = pack_h2(v[i].x, v[i].y);
            uint32_t h1 = pack_h2(v[i].z, v[i].w);
            *reinterpret_cast<uint2*>(base + r * STHB + q * 8) = make_uint2(h0, h1);
        }
    };

    // ---- prologue: A chunk 0 ----
    {
        float4 a[4];
        loadA(tile_rowbase(0), 0, a);
        storeA(0, a);
    }
    CP_WAIT0();      // B resident ready

    float (*scb)[128] = (float(*)[128])(smem + SM_SCB);

    for (int cc = 0; cc < nchunks; cc++) {
        const int buf = cc & 1;
        const uint32_t sa = sbase + SA0 + buf * 18432;
        const int kc = cc & 3;               // K chunk within tile

        __syncthreads();                     // buffer cc ready; prev compute done

        float4 a[4];
        const bool pf = (cc + 1 < nchunks);
        if (pf) {
            int cc2 = cc + 1;
            loadA(tile_rowbase(cc2 >> 2), (cc2 & 3) * 64, a);   // LDG overlaps compute
        }

        // ---- compute chunk: 4 k16-steps, 16 MMAs each; B from resident SMEM ----
#pragma unroll
        for (int ks = 0; ks < 4; ks++) {
            uint32_t Ah[2][4];
#pragma unroll
            for (int mt = 0; mt < 2; mt++)
                LDMX4(Ah[mt], sa + a_off + mt * (16 * STHB) + ks * 32);
            const uint32_t kbyte = (uint32_t)(kc * 128 + ks * 32);
#pragma unroll
            for (int p = 0; p < 4; p++) {
                uint32_t Bh[4];
                LDMX4(Bh, sbase + SB0 + b_off + p * (16 * SBSTR) + kbyte);
#pragma unroll
                for (int mt = 0; mt < 2; mt++) {
                    mma16816(C[mt][2 * p],     Ah[mt], Bh[0], Bh[1]);
                    mma16816(C[mt][2 * p + 1], Ah[mt], Bh[2], Bh[3]);
                }
            }
        }

        // ---- tile boundary: epilogue ----
        if (kc == 3) {
            const int rowbase = tile_rowbase(cc >> 2);
            float pr[2][2];
#pragma unroll
            for (int mt = 0; mt < 2; mt++) {
                float p0 = 0.f, p1 = 0.f;
#pragma unroll
                for (int nt = 0; nt < 8; nt++) {
                    int col0 = wn * 64 + nt * 8 + tg * 2;
                    float bb0 = __ldg(b1 + col0), bb1 = __ldg(b1 + col0 + 1);
                    float ww0 = __ldg(w2 + col0), ww1 = __ldg(w2 + col0 + 1);
                    p0 += fast_tanh(C[mt][nt][0] + bb0) * ww0 + fast_tanh(C[mt][nt][1] + bb1) * ww1;
                    p1 += fast_tanh(C[mt][nt][2] + bb0) * ww0 + fast_tanh(C[mt][nt][3] + bb1) * ww1;
                    C[mt][nt][0] = C[mt][nt][1] = C[mt][nt][2] = C[mt][nt][3] = 0.f;
                }
                p0 += __shfl_xor_sync(0xffffffffu, p0, 1);
                p0 += __shfl_xor_sync(0xffffffffu, p0, 2);
                p1 += __shfl_xor_sync(0xffffffffu, p1, 1);
                p1 += __shfl_xor_sync(0xffffffffu, p1, 2);
                pr[mt][0] = p0; pr[mt][1] = p1;
            }
            __syncthreads();                 // prior-tile scb reads done
            if (tg == 0) {
#pragma unroll
                for (int mt = 0; mt < 2; mt++) {
                    int row = wm * 32 + mt * 16 + gq;
                    scb[wn][row]     = pr[mt][0];
                    scb[wn][row + 8] = pr[mt][1];
                }
            }
            __syncthreads();
            if (t < 128) {
                float sc = scb[0][t] + scb[1][t] + scb[2][t] + scb[3][t];
                int grow = rowbase + t;
                if (grow < N) {
                    g_scores[grow] = sc;
                    if (sc > 0.f)
                        atomicMax(&g_segmax[get_batch(batch, grow, is64)], __float_as_int(sc));
                }
            }
        }

        if (pf) storeA(buf ^ 1, a);          // next-iter sync publishes it
    }
}

// -------- pass C: exp(score - segmax), warp-segmented sum into sumexp --------
__global__ void k_exp_sum(const void* __restrict__ batch, int N)
{
    int i = blockIdx.x * blockDim.x + threadIdx.x;
    int lane = threadIdx.x & 31;
    const bool is64 = batch_is64(batch, N);
    int g = -1;
    float e = 0.f;
    if (i < N) {
        g = get_batch(batch, i, is64);
        float m = __int_as_float(g_segmax[g]);
        e = expf(g_scores[i] - m);
        g_scores[i] = e;
    }
    float v = e;
#pragma unroll
    for (int d = 1; d < 32; d <<= 1) {
        float ov = __shfl_up_sync(0xffffffffu, v, d);
        int   og = __shfl_up_sync(0xffffffffu, g, d);
        if (lane >= d && og == g) v += ov;
    }
    int gn = __shfl_down_sync(0xffffffffu, g, 1);
    if (g >= 0 && (lane == 31 || gn != g))
        atomicAdd(&g_sumexp[g], v);
}

// -------- pass D: reciprocal --------
__global__ void k_inv()
{
    int i = blockIdx.x * blockDim.x + threadIdx.x;
    if (i < G) {
        float s = g_sumexp[i];
        g_inv[i] = (s > 0.f) ? 1.0f / s : 0.f;
    }
}

// -------- pass E: out[g] += x[i] * (exp_i * inv[g]); float4, 4x64-row partitions --------
__global__ void k_scatter(const float* __restrict__ x, const void* __restrict__ batch,
                          float* __restrict__ out, int N)
{
    const int tc = threadIdx.x & 63;       // column group: cols [4tc, 4tc+3]
    const int tp = threadIdx.x >> 6;       // row partition 0..3 (64 rows each)
    const int col = tc * 4;
    int i0 = blockIdx.x * NPB + tp * 64;
    if (i0 >= N) return;
    int i1 = min(i0 + 64, N);
    const bool is64 = batch_is64(batch, N);

    int gfirst = get_batch(batch, i0, is64);
    int gcur = gfirst;
    float4 acc = make_float4(0.f, 0.f, 0.f, 0.f);

    for (int i = i0; i < i1; i++) {
        int g = get_batch(batch, i, is64);
        if (g != gcur) {
            float* o = out + (size_t)gcur * H + col;
            if (gcur == gfirst) {
                atomicAdd(o + 0, acc.x); atomicAdd(o + 1, acc.y);
                atomicAdd(o + 2, acc.z); atomicAdd(o + 3, acc.w);
            } else {
                *reinterpret_cast<float4*>(o) = acc;  // exclusive interior graph
            }
            acc = make_float4(0.f, 0.f, 0.f, 0.f);
            gcur = g;
        }
        float w = g_scores[i] * g_inv[g];
        float4 v = *reinterpret_cast<const float4*>(x + (size_t)i * H + col);
        acc.x += v.x * w; acc.y += v.y * w; acc.z += v.z * w; acc.w += v.w * w;
    }
    float* o = out + (size_t)gcur * H + col;
    atomicAdd(o + 0, acc.x); atomicAdd(o + 1, acc.y);
    atomicAdd(o + 2, acc.z); atomicAdd(o + 3, acc.w);
}

// -------- launch --------
extern "C" void kernel_launch(void* const* d_in, const int* in_sizes, int n_in,
                              void* d_out, int out_size)
{
    const float* x     = (const float*)d_in[0];
    const void*  batch = (const void*)d_in[1];
    const float* W1    = (const float*)d_in[2];
    const float* b1    = (const float*)d_in[3];
    const float* w2    = (const float*)d_in[4];
    float* out = (float*)d_out;

    int N = in_sizes[1];

    int nsm = 148;
    cudaDeviceGetAttribute(&nsm, cudaDevAttrMultiProcessorCount, 0);

    cudaFuncSetAttribute(k_gemm_mma, cudaFuncAttributeMaxDynamicSharedMemorySize, SM_TOT);

    int initBlocks = (out_size + 255) / 256;
    k_init_out<<<initBlocks, 256>>>(out, out_size);   // pos 0
    k_init_seg<<<16, 256>>>();                        // pos 1
    k_prep_w<<<H, H>>>(W1);                           // pos 2
    int T = (N + BRM - 1) / BRM;
    k_gemm_mma<<<nsm, 512, SM_TOT>>>(x, batch, b1, w2, N, T, nsm);  // pos 3 (ncu target)
    k_exp_sum<<<(N + 255) / 256, 256>>>(batch, N);
    k_inv<<<(G + 255) / 256, 256>>>();
    k_scatter<<<(N + NPB - 1) / NPB, 256>>>(x, batch, out, N);
}